// round 15
// baseline (speedup 1.0000x reference)
#include <cuda_runtime.h>
#include <cstdint>

// Problem constants (fixed by the reference setup_inputs)
#define BB 16
#define NN 512
#define DD 256
#define TT 64          // t-tile per block (widened to amortize MARGIN)
#define WMAX 44        // max tokens in window (bound: <=39 at min duration 4)
#define WP 68          // pitch (floats) for w[i][tt]; rows 272B -> 16B aligned
#define MARGIN 44      // excluded tokens have arg >= 121 -> fp32 exp == exact 0
#define NTHR 512

// Scratch (allocation-free rule: __device__ globals)
__device__ float g_c[BB * NN];     // gaussian centers
__device__ float g_ir2[BB * NN];   // 1/r^2
__device__ int   g_e[BB * NN];     // inclusive cumsum of durations
__device__ int   g_start[BB * NN]; // segment starts

// ---------------------------------------------------------------------------
// Kernel A: per-batch warp-scan cumsum + derived params + fused positions
// ---------------------------------------------------------------------------
__global__ void __launch_bounds__(NN)
prep_kernel(const int* __restrict__ dur,
            const float* __restrict__ ranges,
            float* __restrict__ pos_out, int T) {
    __shared__ int se[NN];
    __shared__ int sst[NN];
    __shared__ int part[16];
    int b = blockIdx.x;
    int n = threadIdx.x;
    int lane = n & 31, wid = n >> 5;

    int d = dur[b * NN + n];
    int v = d;
    #pragma unroll
    for (int o = 1; o < 32; o <<= 1) {
        int u = __shfl_up_sync(0xFFFFFFFFu, v, o);
        if (lane >= o) v += u;
    }
    if (lane == 31) part[wid] = v;
    __syncthreads();
    if (wid == 0) {
        int p = (lane < 16) ? part[lane] : 0;
        #pragma unroll
        for (int o = 1; o < 16; o <<= 1) {
            int u = __shfl_up_sync(0xFFFFFFFFu, p, o);
            if (lane >= o) p += u;
        }
        if (lane < 16) part[lane] = p;
    }
    __syncthreads();
    int e = v + (wid ? part[wid - 1] : 0);

    se[n]  = e;
    sst[n] = e - d;
    g_e[b * NN + n]     = e;
    g_start[b * NN + n] = e - d;
    g_c[b * NN + n]     = (float)e - 0.5f * (float)d;
    float r = ranges[b * NN + n];
    g_ir2[b * NN + n]   = 1.0f / (r * r);
    __syncthreads();

    // positions[b,t] = t - start[clip(searchsorted(e, t, 'right'))]
    for (int t = n; t < T; t += NN) {
        int lo = 0, hi = NN;
        while (lo < hi) {
            int m = (lo + hi) >> 1;
            if (se[m] <= t) lo = m + 1; else hi = m;
        }
        int seg = min(lo, NN - 1);
        pos_out[b * T + t] = (float)(t - sst[seg]);
    }
}

// ---------------------------------------------------------------------------
// Kernel B: fused weights + normalized einsum per (batch, 64-t tile).
// R12 structure (cp.async x staging, scalar-FFMA inner loop) with TT=64.
// ---------------------------------------------------------------------------
__global__ void __launch_bounds__(NTHR)
main_kernel(const float* __restrict__ x,
            float* __restrict__ out,      // [B, T, D]
            float* __restrict__ weights,  // [B, N, T]
            int T) {
    extern __shared__ __align__(16) char smbuf[];
    float* sx    = (float*)smbuf;                    // WMAX*DD   (45 KB)
    float* w     = sx + WMAX * DD;                   // WMAX*WP   (12 KB)
    float* invw2 = w + WMAX * WP;                    // TT
    float* sc    = invw2 + TT;                       // WMAX
    float* sir   = sc + WMAX;                        // WMAX
    int*   sn    = (int*)(sir + WMAX);               // 2

    int b    = blockIdx.y;
    int t0   = blockIdx.x * TT;
    int ttmx = min(TT, T - t0);
    int tid  = threadIdx.x;
    int lane = tid & 31, warp = tid >> 5;

    const int* eb  = g_e + b * NN;
    const int* stb = g_start + b * NN;

    // Window binary searches (two threads in different warps)
    if (tid == 0) {
        int key = t0 - MARGIN;            // keep tokens with e[n] >= key
        int lo = 0, hi = NN;
        while (lo < hi) { int m = (lo + hi) >> 1; if (eb[m] < key) lo = m + 1; else hi = m; }
        sn[0] = lo;
    } else if (tid == 32) {
        int key = t0 + ttmx - 1 + MARGIN; // keep tokens with start[n] <= key
        int lo = 0, hi = NN;
        while (lo < hi) { int m = (lo + hi) >> 1; if (stb[m] <= key) lo = m + 1; else hi = m; }
        sn[1] = lo;
    }
    __syncthreads();
    int n0   = sn[0];
    int wlen = sn[1] - n0;
    if (wlen > WMAX) wlen = WMAX;
    if (wlen < 0)    wlen = 0;

    // Stage x window via cp.async (no register round trip); lands during
    // phases 1-2. wait_group + barrier gate phase 4's reads.
    {
        const char* xg = (const char*)((const float4*)(x + (size_t)b * NN * DD)
                                       + (size_t)n0 * (DD / 4));
        uint32_t ss = (uint32_t)__cvta_generic_to_shared(sx);
        int nvec = wlen * (DD / 4);       // float4 count, <= 2816
        for (int idx = tid; idx < nvec; idx += NTHR) {
            asm volatile("cp.async.cg.shared.global [%0], [%1], 16;"
                         :: "r"(ss + idx * 16), "l"(xg + (size_t)idx * 16));
        }
        asm volatile("cp.async.commit_group;");
    }

    if (tid < wlen) {
        sc[tid]  = g_c[b * NN + n0 + tid];
        sir[tid] = g_ir2[b * NN + n0 + tid];
    }
    __syncthreads();

    // Phase 1: w[i][tt] = exp(-ir2 * (t - c)^2) for the window only
    for (int idx = tid; idx < wlen * TT; idx += NTHR) {
        int i = idx >> 6, tt = idx & 63;
        float dt = (float)(t0 + tt) - sc[i];
        w[i * WP + tt] = __expf(-sir[i] * dt * dt);
    }
    __syncthreads();

    // Phase 2: per-t normalizer (16 warps, 4 t's each; stride-WP reads)
    for (int tt = warp; tt < TT; tt += 16) {
        float s = (lane < wlen) ? w[lane * WP + tt] : 0.f;
        if (lane + 32 < wlen) s += w[(lane + 32) * WP + tt];
        #pragma unroll
        for (int o = 16; o; o >>= 1) s += __shfl_xor_sync(0xFFFFFFFFu, s, o);
        if (lane == 0) invw2[tt] = 1.0f / (s + 1e-20f);
    }
    // Drain this thread's async copies, then barrier -> sx visible to all.
    asm volatile("cp.async.wait_group 0;");
    __syncthreads();

    // Phase 3: weights [B,N,T] — mostly-zero rows, streaming float4 stores
    float* wout = weights + (size_t)b * NN * T + t0;
    if (ttmx == TT && (T & 3) == 0) {
        // vector path: thread -> (row n, quad q of 4 t's); 16 quads/row
        for (int idx = tid; idx < NN * 16; idx += NTHR) {
            int n = idx >> 4, q = idx & 15;
            float4 v = make_float4(0.f, 0.f, 0.f, 0.f);
            int i = n - n0;
            if ((unsigned)i < (unsigned)wlen) {
                float4 wv = *(const float4*)&w[i * WP + q * 4];
                float4 iv = *(const float4*)&invw2[q * 4];
                v = make_float4(wv.x * iv.x, wv.y * iv.y, wv.z * iv.z, wv.w * iv.w);
            }
            __stcs(((float4*)(wout + (size_t)n * T)) + q, v);
        }
    } else {
        for (int idx = tid; idx < NN * TT; idx += NTHR) {
            int n = idx >> 6, tt = idx & 63;
            if (tt < ttmx) {
                int i = n - n0;
                float v = ((unsigned)i < (unsigned)wlen) ? w[i * WP + tt] * invw2[tt] : 0.f;
                __stcs(wout + (size_t)n * T + tt, v);
            }
        }
    }

    // Phase 4: out[b, t0:t0+64, :] = sum_i w[i][tt]*invw2[tt] * x[b,n0+i,:]
    // Thread: 4 consecutive d (float4) x 8 t's -> 32 accumulators.
    // x reads: conflict-free LDS.128 from sx; w reads: 2 warp-uniform LDS.128.
    int dg = tid & 63;   // d-group (d = dg*4)
    int tg = tid >> 6;   // t-group (t's = tg*8 .. tg*8+7), 8 groups
    float4 acc[8];
    #pragma unroll
    for (int j = 0; j < 8; j++) acc[j] = make_float4(0.f, 0.f, 0.f, 0.f);

    const float4* xs = (const float4*)sx + dg;
    for (int i = 0; i < wlen; i++) {
        float4 xv = xs[i * (DD / 4)];
        const float4* wrow = (const float4*)&w[i * WP] + tg * 2;
        float4 wa = wrow[0];
        float4 wb = wrow[1];
        acc[0].x += wa.x * xv.x; acc[0].y += wa.x * xv.y; acc[0].z += wa.x * xv.z; acc[0].w += wa.x * xv.w;
        acc[1].x += wa.y * xv.x; acc[1].y += wa.y * xv.y; acc[1].z += wa.y * xv.z; acc[1].w += wa.y * xv.w;
        acc[2].x += wa.z * xv.x; acc[2].y += wa.z * xv.y; acc[2].z += wa.z * xv.z; acc[2].w += wa.z * xv.w;
        acc[3].x += wa.w * xv.x; acc[3].y += wa.w * xv.y; acc[3].z += wa.w * xv.z; acc[3].w += wa.w * xv.w;
        acc[4].x += wb.x * xv.x; acc[4].y += wb.x * xv.y; acc[4].z += wb.x * xv.z; acc[4].w += wb.x * xv.w;
        acc[5].x += wb.y * xv.x; acc[5].y += wb.y * xv.y; acc[5].z += wb.y * xv.z; acc[5].w += wb.y * xv.w;
        acc[6].x += wb.z * xv.x; acc[6].y += wb.z * xv.y; acc[6].z += wb.z * xv.z; acc[6].w += wb.z * xv.w;
        acc[7].x += wb.w * xv.x; acc[7].y += wb.w * xv.y; acc[7].z += wb.w * xv.z; acc[7].w += wb.w * xv.w;
    }

    float* ob = out + (size_t)b * T * DD + (size_t)t0 * DD + dg * 4;
    #pragma unroll
    for (int j = 0; j < 8; j++) {
        int tt = tg * 8 + j;
        if (tt < ttmx) {
            float s = invw2[tt];
            float4 v = make_float4(acc[j].x * s, acc[j].y * s,
                                   acc[j].z * s, acc[j].w * s);
            __stcs((float4*)(ob + (size_t)tt * DD), v);
        }
    }
}

// ---------------------------------------------------------------------------
extern "C" void kernel_launch(void* const* d_in, const int* in_sizes, int n_in,
                              void* d_out, int out_size) {
    const float* x   = (const float*)d_in[0];
    const int*   dur = (const int*)d_in[1];
    const float* rng = (const float*)d_in[2];

    // out = positions[B,T] ++ out[B,T,D] ++ weights[B,N,T], all float32
    int T = out_size / (BB * (1 + DD) + BB * NN);

    float* pos_out = (float*)d_out;
    float* einsum  = pos_out + (size_t)BB * T;
    float* wts     = einsum + (size_t)BB * T * DD;

    prep_kernel<<<BB, NN>>>(dur, rng, pos_out, T);

    size_t smem = (size_t)(WMAX * DD + WMAX * WP + TT + 2 * WMAX) * sizeof(float)
                + 2 * sizeof(int) + 64;
    cudaFuncSetAttribute(main_kernel, cudaFuncAttributeMaxDynamicSharedMemorySize,
                         (int)smem);
    int nTiles = (T + TT - 1) / TT;
    dim3 grid(nTiles, BB);
    main_kernel<<<grid, NTHR, smem>>>(x, einsum, wts, T);
}

// round 16
// speedup vs baseline: 1.0348x; 1.0348x over previous
#include <cuda_runtime.h>
#include <cstdint>

// Problem constants (fixed by the reference setup_inputs)
#define BB 16
#define NN 512
#define DD 256
#define TT 32          // t-tile per block
#define WMAX 36        // max tokens in window (bound: <=31 at min duration 4)
#define WP 36          // pitch (floats) for w[i][tt]; rows 144B -> 16B aligned
#define MARGIN 44      // excluded tokens have arg >= 121 -> fp32 exp == exact 0

// Scratch (allocation-free rule: __device__ globals)
__device__ float g_c[BB * NN];     // gaussian centers
__device__ float g_ir2[BB * NN];   // 1/r^2
__device__ int   g_e[BB * NN];     // inclusive cumsum of durations
__device__ int   g_start[BB * NN]; // segment starts

// ---------------------------------------------------------------------------
// Kernel A: per-batch warp-scan cumsum + derived params + fused positions
// ---------------------------------------------------------------------------
__global__ void __launch_bounds__(NN)
prep_kernel(const int* __restrict__ dur,
            const float* __restrict__ ranges,
            float* __restrict__ pos_out, int T) {
    __shared__ int se[NN];
    __shared__ int sst[NN];
    __shared__ int part[16];
    int b = blockIdx.x;
    int n = threadIdx.x;
    int lane = n & 31, wid = n >> 5;

    int d = dur[b * NN + n];
    int v = d;
    #pragma unroll
    for (int o = 1; o < 32; o <<= 1) {
        int u = __shfl_up_sync(0xFFFFFFFFu, v, o);
        if (lane >= o) v += u;
    }
    if (lane == 31) part[wid] = v;
    __syncthreads();
    if (wid == 0) {
        int p = (lane < 16) ? part[lane] : 0;
        #pragma unroll
        for (int o = 1; o < 16; o <<= 1) {
            int u = __shfl_up_sync(0xFFFFFFFFu, p, o);
            if (lane >= o) p += u;
        }
        if (lane < 16) part[lane] = p;
    }
    __syncthreads();
    int e = v + (wid ? part[wid - 1] : 0);

    se[n]  = e;
    sst[n] = e - d;
    g_e[b * NN + n]     = e;
    g_start[b * NN + n] = e - d;
    g_c[b * NN + n]     = (float)e - 0.5f * (float)d;
    float r = ranges[b * NN + n];
    g_ir2[b * NN + n]   = 1.0f / (r * r);
    __syncthreads();

    // positions[b,t] = t - start[clip(searchsorted(e, t, 'right'))]
    for (int t = n; t < T; t += NN) {
        int lo = 0, hi = NN;
        while (lo < hi) {
            int m = (lo + hi) >> 1;
            if (se[m] <= t) lo = m + 1; else hi = m;
        }
        int seg = min(lo, NN - 1);
        pos_out[b * T + t] = (float)(t - sst[seg]);
    }
}

// ---------------------------------------------------------------------------
// Kernel B: fused weights + normalized einsum (R12 winner; ONLY change:
// per-t-group [i0,i1) bounds in phase 4 — ~20% fewer einsum iterations)
// ---------------------------------------------------------------------------
__global__ void __launch_bounds__(256)
main_kernel(const float* __restrict__ x,
            float* __restrict__ out,      // [B, T, D]
            float* __restrict__ weights,  // [B, N, T]
            int T) {
    __shared__ __align__(16) float sx[WMAX * DD];  // staged x rows (36 KB)
    __shared__ __align__(16) float w[WMAX * WP];   // w[i*WP + tt]
    __shared__ __align__(16) float invw2[TT];
    __shared__ float sc[WMAX];
    __shared__ float sir[WMAX];
    __shared__ int   gi0[4], gi1[4];               // per-t-group token bounds

    int b    = blockIdx.y;
    int t0   = blockIdx.x * TT;
    int ttmx = min(TT, T - t0);
    int tid  = threadIdx.x;
    int lane = tid & 31, warp = tid >> 5;

    const int* eb  = g_e + b * NN;
    const int* stb = g_start + b * NN;

    // Per-group window searches (threads 0-7; group tg covers t's
    // [t0+8tg, min(t0+8tg+7, t0+ttmx-1)]). Tile bounds = gi0[0] / gi1[3].
    if (tid < 8) {
        int tg = tid & 3;
        if (tid < 4) {
            int key = t0 + 8 * tg - MARGIN;           // first n with e[n] >= key
            int lo = 0, hi = NN;
            while (lo < hi) { int m = (lo + hi) >> 1; if (eb[m] < key) lo = m + 1; else hi = m; }
            gi0[tg] = lo;
        } else {
            int thi = min(8 * tg + 7, ttmx - 1);
            int key = t0 + thi + MARGIN;              // first n with start[n] > key
            int lo = 0, hi = NN;
            while (lo < hi) { int m = (lo + hi) >> 1; if (stb[m] <= key) lo = m + 1; else hi = m; }
            gi1[tg] = lo;
        }
    }
    __syncthreads();
    int n0   = gi0[0];
    int wlen = gi1[3] - n0;
    if (wlen > WMAX) wlen = WMAX;
    if (wlen < 0)    wlen = 0;

    // Stage x window via cp.async: no register round trip; lands during
    // phases 1-2. wait_group + existing barrier gate phase 4's reads.
    {
        const char* xg = (const char*)((const float4*)(x + (size_t)b * NN * DD)
                                       + (size_t)n0 * (DD / 4));
        uint32_t ss = (uint32_t)__cvta_generic_to_shared(sx);
        int nvec = wlen * (DD / 4);       // float4 count, <= 2304
        for (int idx = tid; idx < nvec; idx += 256) {
            asm volatile("cp.async.cg.shared.global [%0], [%1], 16;"
                         :: "r"(ss + idx * 16), "l"(xg + (size_t)idx * 16));
        }
        asm volatile("cp.async.commit_group;");
    }

    if (tid < wlen) {
        sc[tid]  = g_c[b * NN + n0 + tid];
        sir[tid] = g_ir2[b * NN + n0 + tid];
    }
    __syncthreads();

    // Phase 1: w[i][tt] = exp(-ir2 * (t - c)^2) for the window only
    for (int idx = tid; idx < wlen * TT; idx += 256) {
        int i = idx >> 5, tt = idx & 31;
        float dt = (float)(t0 + tt) - sc[i];
        w[i * WP + tt] = __expf(-sir[i] * dt * dt);
    }
    __syncthreads();

    // Phase 2: per-t normalizer (stride-WP reads; tiny phase, conflicts ok)
    for (int tt = warp; tt < TT; tt += 8) {
        float s = (lane < wlen) ? w[lane * WP + tt] : 0.f;
        if (lane + 32 < wlen) s += w[(lane + 32) * WP + tt];
        #pragma unroll
        for (int o = 16; o; o >>= 1) s += __shfl_xor_sync(0xFFFFFFFFu, s, o);
        if (lane == 0) invw2[tt] = 1.0f / (s + 1e-20f);
    }
    // Drain this thread's async copies, then barrier -> sx visible to all.
    asm volatile("cp.async.wait_group 0;");
    __syncthreads();

    // Phase 3: weights [B,N,T] — mostly-zero rows, streaming float4 stores
    float* wout = weights + (size_t)b * NN * T + t0;
    if (ttmx == TT && (T & 3) == 0) {
        // vector path: thread -> (row n, quad q of 4 t's)
        for (int idx = tid; idx < NN * 8; idx += 256) {
            int n = idx >> 3, q = idx & 7;
            float4 v = make_float4(0.f, 0.f, 0.f, 0.f);
            int i = n - n0;
            if ((unsigned)i < (unsigned)wlen) {
                float4 wv = *(const float4*)&w[i * WP + q * 4];
                float4 iv = *(const float4*)&invw2[q * 4];
                v = make_float4(wv.x * iv.x, wv.y * iv.y, wv.z * iv.z, wv.w * iv.w);
            }
            __stcs(((float4*)(wout + (size_t)n * T)) + q, v);
        }
    } else {
        for (int idx = tid; idx < NN * TT; idx += 256) {
            int n = idx >> 5, tt = idx & 31;
            if (tt < ttmx) {
                int i = n - n0;
                float v = ((unsigned)i < (unsigned)wlen) ? w[i * WP + tt] * invw2[tt] : 0.f;
                __stcs(wout + (size_t)n * T + tt, v);
            }
        }
    }

    // Phase 4: out[b, t0+tt, :] = sum_i w[i][tt]*invw2[tt] * x[b,n0+i,:]
    // Thread: 4 consecutive d (float4) x 8 t's -> 32 accumulators.
    // Group-local bounds [i0, i1): tokens outside contribute exact fp32 zero
    // to every t in this group (same underflow bound as the tile proof).
    int dg = tid & 63;   // d-group (d = dg*4)
    int tg = tid >> 6;   // t-group (t's = tg*8 .. tg*8+7), uniform per warp
    float4 acc[8];
    #pragma unroll
    for (int j = 0; j < 8; j++) acc[j] = make_float4(0.f, 0.f, 0.f, 0.f);

    int i0 = gi0[tg] - n0;  if (i0 < 0) i0 = 0;
    int i1 = gi1[tg] - n0;  if (i1 > wlen) i1 = wlen;

    const float4* xs = (const float4*)sx + dg;
    for (int i = i0; i < i1; i++) {
        float4 xv = xs[i * (DD / 4)];
        const float4* wrow = (const float4*)&w[i * WP] + tg * 2;
        float4 wa = wrow[0];
        float4 wb = wrow[1];
        acc[0].x += wa.x * xv.x; acc[0].y += wa.x * xv.y; acc[0].z += wa.x * xv.z; acc[0].w += wa.x * xv.w;
        acc[1].x += wa.y * xv.x; acc[1].y += wa.y * xv.y; acc[1].z += wa.y * xv.z; acc[1].w += wa.y * xv.w;
        acc[2].x += wa.z * xv.x; acc[2].y += wa.z * xv.y; acc[2].z += wa.z * xv.z; acc[2].w += wa.z * xv.w;
        acc[3].x += wa.w * xv.x; acc[3].y += wa.w * xv.y; acc[3].z += wa.w * xv.z; acc[3].w += wa.w * xv.w;
        acc[4].x += wb.x * xv.x; acc[4].y += wb.x * xv.y; acc[4].z += wb.x * xv.z; acc[4].w += wb.x * xv.w;
        acc[5].x += wb.y * xv.x; acc[5].y += wb.y * xv.y; acc[5].z += wb.y * xv.z; acc[5].w += wb.y * xv.w;
        acc[6].x += wb.z * xv.x; acc[6].y += wb.z * xv.y; acc[6].z += wb.z * xv.z; acc[6].w += wb.z * xv.w;
        acc[7].x += wb.w * xv.x; acc[7].y += wb.w * xv.y; acc[7].z += wb.w * xv.z; acc[7].w += wb.w * xv.w;
    }

    float* ob = out + (size_t)b * T * DD + (size_t)t0 * DD + dg * 4;
    #pragma unroll
    for (int j = 0; j < 8; j++) {
        int tt = tg * 8 + j;
        if (tt < ttmx) {
            float s = invw2[tt];
            float4 v = make_float4(acc[j].x * s, acc[j].y * s,
                                   acc[j].z * s, acc[j].w * s);
            __stcs((float4*)(ob + (size_t)tt * DD), v);
        }
    }
}

// ---------------------------------------------------------------------------
extern "C" void kernel_launch(void* const* d_in, const int* in_sizes, int n_in,
                              void* d_out, int out_size) {
    const float* x   = (const float*)d_in[0];
    const int*   dur = (const int*)d_in[1];
    const float* rng = (const float*)d_in[2];

    // out = positions[B,T] ++ out[B,T,D] ++ weights[B,N,T], all float32
    int T = out_size / (BB * (1 + DD) + BB * NN);

    float* pos_out = (float*)d_out;
    float* einsum  = pos_out + (size_t)BB * T;
    float* wts     = einsum + (size_t)BB * T * DD;

    prep_kernel<<<BB, NN>>>(dur, rng, pos_out, T);

    int nTiles = (T + TT - 1) / TT;
    dim3 grid(nTiles, BB);
    main_kernel<<<grid, 256>>>(x, einsum, wts, T);
}

// round 17
// speedup vs baseline: 1.1224x; 1.0846x over previous
#include <cuda_runtime.h>
#include <cstdint>

// Problem constants (fixed by the reference setup_inputs)
#define BB 16
#define NN 512
#define DD 256
#define TT 32          // t-tile per block
#define WMAX 36        // max tokens in window (bound: <=31 at min duration 4)
#define WP 36          // pitch (floats) for w[i][tt]; rows 144B -> 16B aligned
#define MARGIN 44      // excluded tokens have arg >= 121 -> fp32 exp == exact 0

// Scratch (allocation-free rule: __device__ globals)
__device__ float g_c[BB * NN];     // gaussian centers
__device__ float g_ir2[BB * NN];   // 1/r^2
__device__ int   g_e[BB * NN];     // inclusive cumsum of durations
__device__ int   g_start[BB * NN]; // segment starts

// ---------------------------------------------------------------------------
// Kernel A: per-batch warp-scan cumsum + derived per-token params (scan only;
// positions moved into main_kernel)
// ---------------------------------------------------------------------------
__global__ void __launch_bounds__(NN)
prep_kernel(const int* __restrict__ dur,
            const float* __restrict__ ranges) {
    __shared__ int part[16];
    int b = blockIdx.x;
    int n = threadIdx.x;
    int lane = n & 31, wid = n >> 5;

    int d = dur[b * NN + n];
    int v = d;
    #pragma unroll
    for (int o = 1; o < 32; o <<= 1) {
        int u = __shfl_up_sync(0xFFFFFFFFu, v, o);
        if (lane >= o) v += u;
    }
    if (lane == 31) part[wid] = v;
    __syncthreads();
    if (wid == 0) {
        int p = (lane < 16) ? part[lane] : 0;
        #pragma unroll
        for (int o = 1; o < 16; o <<= 1) {
            int u = __shfl_up_sync(0xFFFFFFFFu, p, o);
            if (lane >= o) p += u;
        }
        if (lane < 16) part[lane] = p;
    }
    __syncthreads();
    int e = v + (wid ? part[wid - 1] : 0);

    g_e[b * NN + n]     = e;
    g_start[b * NN + n] = e - d;
    g_c[b * NN + n]     = (float)e - 0.5f * (float)d;
    float r = ranges[b * NN + n];
    g_ir2[b * NN + n]   = 1.0f / (r * r);
}

// ---------------------------------------------------------------------------
// Kernel B: fused positions + weights + normalized einsum (R12 winner; ONLY
// change: warp 1 computes this tile's positions via global binary search,
// overlapped with cp.async staging and phase 1)
// ---------------------------------------------------------------------------
__global__ void __launch_bounds__(256)
main_kernel(const float* __restrict__ x,
            float* __restrict__ pos_out,  // [B, T]
            float* __restrict__ out,      // [B, T, D]
            float* __restrict__ weights,  // [B, N, T]
            int T) {
    __shared__ __align__(16) float sx[WMAX * DD];  // staged x rows (36 KB)
    __shared__ __align__(16) float w[WMAX * WP];   // w[i*WP + tt]
    __shared__ __align__(16) float invw2[TT];
    __shared__ float sc[WMAX];
    __shared__ float sir[WMAX];
    __shared__ int   sn0, sn1;

    int b    = blockIdx.y;
    int t0   = blockIdx.x * TT;
    int ttmx = min(TT, T - t0);
    int tid  = threadIdx.x;
    int lane = tid & 31, warp = tid >> 5;

    const int* eb  = g_e + b * NN;
    const int* stb = g_start + b * NN;

    // Window binary searches (two threads in different warps)
    if (tid == 0) {
        int key = t0 - MARGIN;            // keep tokens with e[n] >= key
        int lo = 0, hi = NN;
        while (lo < hi) { int m = (lo + hi) >> 1; if (eb[m] < key) lo = m + 1; else hi = m; }
        sn0 = lo;
    } else if (tid == 32) {
        int key = t0 + ttmx - 1 + MARGIN; // keep tokens with start[n] <= key
        int lo = 0, hi = NN;
        while (lo < hi) { int m = (lo + hi) >> 1; if (stb[m] <= key) lo = m + 1; else hi = m; }
        sn1 = lo;
    }
    __syncthreads();
    int n0   = sn0;
    int wlen = sn1 - n0;
    if (wlen > WMAX) wlen = WMAX;
    if (wlen < 0)    wlen = 0;

    // Stage x window via cp.async: no register round trip; lands during
    // phases 1-2. wait_group + existing barrier gate phase 4's reads.
    {
        const char* xg = (const char*)((const float4*)(x + (size_t)b * NN * DD)
                                       + (size_t)n0 * (DD / 4));
        uint32_t ss = (uint32_t)__cvta_generic_to_shared(sx);
        int nvec = wlen * (DD / 4);       // float4 count, <= 2304
        for (int idx = tid; idx < nvec; idx += 256) {
            asm volatile("cp.async.cg.shared.global [%0], [%1], 16;"
                         :: "r"(ss + idx * 16), "l"(xg + (size_t)idx * 16));
        }
        asm volatile("cp.async.commit_group;");
    }

    // Positions (warp 1, overlapped with staging + phase 1): GLOBAL binary
    // search — exact reference clip semantics for every t incl. tail tiles.
    if (warp == 1 && lane < ttmx) {
        int t = t0 + lane;
        int lo = 0, hi = NN;
        while (lo < hi) { int m = (lo + hi) >> 1; if (eb[m] <= t) lo = m + 1; else hi = m; }
        int seg = min(lo, NN - 1);
        pos_out[b * T + t] = (float)(t - stb[seg]);
    }

    if (tid < wlen) {
        sc[tid]  = g_c[b * NN + n0 + tid];
        sir[tid] = g_ir2[b * NN + n0 + tid];
    }
    __syncthreads();

    // Phase 1: w[i][tt] = exp(-ir2 * (t - c)^2) for the window only
    for (int idx = tid; idx < wlen * TT; idx += 256) {
        int i = idx >> 5, tt = idx & 31;
        float dt = (float)(t0 + tt) - sc[i];
        w[i * WP + tt] = __expf(-sir[i] * dt * dt);
    }
    __syncthreads();

    // Phase 2: per-t normalizer (stride-WP reads; tiny phase, conflicts ok)
    for (int tt = warp; tt < TT; tt += 8) {
        float s = (lane < wlen) ? w[lane * WP + tt] : 0.f;
        if (lane + 32 < wlen) s += w[(lane + 32) * WP + tt];
        #pragma unroll
        for (int o = 16; o; o >>= 1) s += __shfl_xor_sync(0xFFFFFFFFu, s, o);
        if (lane == 0) invw2[tt] = 1.0f / (s + 1e-20f);
    }
    // Drain this thread's async copies, then barrier -> sx visible to all.
    asm volatile("cp.async.wait_group 0;");
    __syncthreads();

    // Phase 3: weights [B,N,T] — mostly-zero rows, streaming float4 stores
    float* wout = weights + (size_t)b * NN * T + t0;
    if (ttmx == TT && (T & 3) == 0) {
        // vector path: thread -> (row n, quad q of 4 t's)
        for (int idx = tid; idx < NN * 8; idx += 256) {
            int n = idx >> 3, q = idx & 7;
            float4 v = make_float4(0.f, 0.f, 0.f, 0.f);
            int i = n - n0;
            if ((unsigned)i < (unsigned)wlen) {
                float4 wv = *(const float4*)&w[i * WP + q * 4];
                float4 iv = *(const float4*)&invw2[q * 4];
                v = make_float4(wv.x * iv.x, wv.y * iv.y, wv.z * iv.z, wv.w * iv.w);
            }
            __stcs(((float4*)(wout + (size_t)n * T)) + q, v);
        }
    } else {
        for (int idx = tid; idx < NN * TT; idx += 256) {
            int n = idx >> 5, tt = idx & 31;
            if (tt < ttmx) {
                int i = n - n0;
                float v = ((unsigned)i < (unsigned)wlen) ? w[i * WP + tt] * invw2[tt] : 0.f;
                __stcs(wout + (size_t)n * T + tt, v);
            }
        }
    }

    // Phase 4: out[b, t0+tt, :] = sum_i w[i][tt]*invw2[tt] * x[b,n0+i,:]
    // Thread: 4 consecutive d (float4) x 8 t's -> 32 accumulators.
    // x reads: conflict-free LDS.128 from sx; w reads: 2 warp-uniform LDS.128.
    int dg = tid & 63;   // d-group (d = dg*4)
    int tg = tid >> 6;   // t-group (t's = tg*8 .. tg*8+7)
    float4 acc[8];
    #pragma unroll
    for (int j = 0; j < 8; j++) acc[j] = make_float4(0.f, 0.f, 0.f, 0.f);

    const float4* xs = (const float4*)sx + dg;
    for (int i = 0; i < wlen; i++) {
        float4 xv = xs[i * (DD / 4)];
        const float4* wrow = (const float4*)&w[i * WP] + tg * 2;
        float4 wa = wrow[0];
        float4 wb = wrow[1];
        acc[0].x += wa.x * xv.x; acc[0].y += wa.x * xv.y; acc[0].z += wa.x * xv.z; acc[0].w += wa.x * xv.w;
        acc[1].x += wa.y * xv.x; acc[1].y += wa.y * xv.y; acc[1].z += wa.y * xv.z; acc[1].w += wa.y * xv.w;
        acc[2].x += wa.z * xv.x; acc[2].y += wa.z * xv.y; acc[2].z += wa.z * xv.z; acc[2].w += wa.z * xv.w;
        acc[3].x += wa.w * xv.x; acc[3].y += wa.w * xv.y; acc[3].z += wa.w * xv.z; acc[3].w += wa.w * xv.w;
        acc[4].x += wb.x * xv.x; acc[4].y += wb.x * xv.y; acc[4].z += wb.x * xv.z; acc[4].w += wb.x * xv.w;
        acc[5].x += wb.y * xv.x; acc[5].y += wb.y * xv.y; acc[5].z += wb.y * xv.z; acc[5].w += wb.y * xv.w;
        acc[6].x += wb.z * xv.x; acc[6].y += wb.z * xv.y; acc[6].z += wb.z * xv.z; acc[6].w += wb.z * xv.w;
        acc[7].x += wb.w * xv.x; acc[7].y += wb.w * xv.y; acc[7].z += wb.w * xv.z; acc[7].w += wb.w * xv.w;
    }

    float* ob = out + (size_t)b * T * DD + (size_t)t0 * DD + dg * 4;
    #pragma unroll
    for (int j = 0; j < 8; j++) {
        int tt = tg * 8 + j;
        if (tt < ttmx) {
            float s = invw2[tt];
            float4 v = make_float4(acc[j].x * s, acc[j].y * s,
                                   acc[j].z * s, acc[j].w * s);
            __stcs((float4*)(ob + (size_t)tt * DD), v);
        }
    }
}

// ---------------------------------------------------------------------------
extern "C" void kernel_launch(void* const* d_in, const int* in_sizes, int n_in,
                              void* d_out, int out_size) {
    const float* x   = (const float*)d_in[0];
    const int*   dur = (const int*)d_in[1];
    const float* rng = (const float*)d_in[2];

    // out = positions[B,T] ++ out[B,T,D] ++ weights[B,N,T], all float32
    int T = out_size / (BB * (1 + DD) + BB * NN);

    float* pos_out = (float*)d_out;
    float* einsum  = pos_out + (size_t)BB * T;
    float* wts     = einsum + (size_t)BB * T * DD;

    prep_kernel<<<BB, NN>>>(dur, rng);

    int nTiles = (T + TT - 1) / TT;
    dim3 grid(nTiles, BB);
    main_kernel<<<grid, 256>>>(x, pos_out, einsum, wts, T);
}